// round 14
// baseline (speedup 1.0000x reference)
#include <cuda_runtime.h>
#include <cuda_bf16.h>
#include <cstdint>

// Conv2d 3x3 s1 p1 NCHW, implicit GEMM, mma.sync tf32.
// A: pre-converted tf32 fragment-ordered table (g_wtf, L2-resident), LDG.128,
//    ping-pong buffered across taps.
// B: halo tile 8ch x 18x18 in smem (16B cp.async), fragments ping-pong
//    buffered across taps so LDS+CVT latency hides under HMMA.
// CTA: 128ko x 256px (16x16 tile, one image), 256 thr, 8 warps, warp 64x64.

#define HW    112
#define IMG   (HW * HW)
#define KTOT  576
#define KOUT  128

#define H_ROW   24                       // halo row pitch (words)
#define H_CH    440                      // per-channel words; 440%32==24
#define H_BYTES (8 * H_CH * 4)           // 14080
#define NBUF    4
#define SMEM_TOTAL (NBUF * H_BYTES)      // 56320

__device__ uint32_t g_wtf[8 * 9 * 2 * 4 * 128];   // 288 KB

__device__ __forceinline__ uint32_t cvt_tf32(float x) {
    uint32_t r;
    asm("cvt.rna.tf32.f32 %0, %1;" : "=r"(r) : "f"(x));
    return r;
}
__device__ __forceinline__ uint32_t smem_u32(const void* p) {
    uint32_t a;
    asm("{ .reg .u64 t; cvta.to.shared.u64 t, %1; cvt.u32.u64 %0, t; }" : "=r"(a) : "l"(p));
    return a;
}
__device__ __forceinline__ float lds_f32(uint32_t a) {
    float v;
    asm volatile("ld.shared.f32 %0, [%1];" : "=f"(v) : "r"(a));
    return v;
}
__device__ __forceinline__ void cpa16z(uint32_t dst, const float* src, int sz) {
    asm volatile("cp.async.cg.shared.global [%0], [%1], 16, %2;"
                 :: "r"(dst), "l"(src), "r"(sz));
}
__device__ __forceinline__ void cpa4(uint32_t dst, const float* src, int sz) {
    asm volatile("cp.async.ca.shared.global [%0], [%1], 4, %2;"
                 :: "r"(dst), "l"(src), "r"(sz));
}
__device__ __forceinline__ void mma8(float* d, const uint4& a, const uint32_t* b) {
    asm volatile(
        "mma.sync.aligned.m16n8k8.row.col.f32.tf32.tf32.f32 "
        "{%0,%1,%2,%3}, {%4,%5,%6,%7}, {%8,%9}, {%0,%1,%2,%3};"
        : "+f"(d[0]), "+f"(d[1]), "+f"(d[2]), "+f"(d[3])
        : "r"(a.x), "r"(a.y), "r"(a.z), "r"(a.w), "r"(b[0]), "r"(b[1]));
}

// ---- prep: w[ko][k] f32 -> g_wtf fragment-ordered tf32 ----
__global__ void prep_w(const float* __restrict__ w) {
    const int i  = blockIdx.x * 256 + threadIdx.x;   // 0..73727
    const int ko = i / KTOT;
    const int k  = i - ko * KTOT;
    const int wm = ko >> 6, mi = (ko >> 4) & 3, h = (ko >> 3) & 1, g = ko & 7;
    const int cc = k / 72;
    const int kr = k - cc * 72;
    const int ch = kr / 9;
    const int t  = kr - ch * 9;
    const int tig = ch & 3, c1 = ch >> 2;
    const int dst = ((((cc * 9 + t) * 2 + wm) * 4 + mi) << 7) + (g * 4 + tig) * 4 +
                    (h + 2 * c1);
    g_wtf[dst] = cvt_tf32(w[i]);
}

__global__ __launch_bounds__(256, 1)
void conv_mma_wreg2(const float* __restrict__ x,
                    const float* __restrict__ bias,
                    float* __restrict__ out)
{
    extern __shared__ __align__(16) char dsm[];
    const uint32_t sb = smem_u32(dsm);

    const int tid  = threadIdx.x;
    const int warp = tid >> 5;
    const int lane = tid & 31;
    const int g    = lane >> 2;
    const int tig  = lane & 3;
    const int warp_m = warp >> 2;        // 0..1
    const int warp_n = warp & 3;         // 0..3

    const int tile = blockIdx.x;         // 0..48
    const int n    = blockIdx.y;         // 0..31
    const int py0  = (tile / 7) * 16;
    const int px0  = (tile % 7) * 16;

    const float* xn = x + (size_t)n * 64 * IMG;

    // ---- B staging precompute: thread<144 owns one (ch,row) halo row ----
    const bool  hact = tid < 144;
    const int   hch  = hact ? tid / 18 : 0;
    const int   hrow = hact ? tid - hch * 18 : 0;
    const int   gy   = py0 - 1 + hrow;
    const bool  gyok = hact && ((unsigned)gy < (unsigned)HW);
    const int   srco = hch * IMG + (gyok ? gy : 0) * HW;
    const uint32_t hdb = (uint32_t)((hch * H_CH + hrow * H_ROW + 3) * 4);
    const int   szq  = gyok ? 16 : 0;
    const int   szl  = (gyok && px0 > 0) ? 4 : 0;
    const int   szt  = (gyok && px0 + 16 < HW) ? 4 : 0;

    auto stage = [&](int cc, int buf) {
        if (hact) {
            const uint32_t db = sb + (uint32_t)buf * H_BYTES + hdb;
            const float* sr = xn + cc * 8 * IMG + srco;
            cpa4(db, sr + px0 - 1, szl);
#pragma unroll
            for (int q = 0; q < 4; q++)
                cpa16z(db + (uint32_t)((1 + 4 * q) * 4), sr + px0 + 4 * q, szq);
            cpa4(db + 17 * 4, sr + px0 + 16, szt);
        }
        asm volatile("cp.async.commit_group;" ::: "memory");
    };

    // ---- A fragment load (from g_wtf) ----
    auto ldA = [&](int cc, int t, uint4 a[4]) {
        const uint4* p = (const uint4*)g_wtf +
                         (size_t)(((cc * 9 + t) * 2 + warp_m) * 4) * 32 + lane;
        a[0] = __ldg(p);
        a[1] = __ldg(p + 32);
        a[2] = __ldg(p + 64);
        a[3] = __ldg(p + 96);
    };

    // B fragment base (bytes) and per-tap load
    const uint32_t boff0 = (uint32_t)((3 + tig * H_CH + warp_n * 4 * H_ROW + g) * 4);
    auto ldB = [&](uint32_t b0, int t, uint32_t bf[8][2]) {
        const int dyt = t / 3, dxt = t - dyt * 3;   // compile-time under unroll
#pragma unroll
        for (int ni = 0; ni < 8; ni++) {
            const uint32_t bm = b0 +
                (uint32_t)((((ni >> 1) + dyt) * H_ROW + (ni & 1) * 8 + dxt) * 4);
            bf[ni][0] = cvt_tf32(lds_f32(bm));
            bf[ni][1] = cvt_tf32(lds_f32(bm + 4 * H_CH * 4));
        }
    };

    float acc[4][8][4];
#pragma unroll
    for (int mi = 0; mi < 4; mi++)
#pragma unroll
        for (int ni = 0; ni < 8; ni++)
#pragma unroll
            for (int r = 0; r < 4; r++) acc[mi][ni][r] = 0.0f;

    uint4 afb[2][4];
    ldA(0, 0, afb[0]);

    // ---- pipeline ----
    stage(0, 0);
    stage(1, 1);
    stage(2, 2);
#pragma unroll 1
    for (int cc = 0; cc < 8; cc++) {
        if (cc < 6)       asm volatile("cp.async.wait_group 2;" ::: "memory");
        else if (cc == 6) asm volatile("cp.async.wait_group 1;" ::: "memory");
        else              asm volatile("cp.async.wait_group 0;" ::: "memory");
        __syncthreads();
        if (cc + 3 < 8) stage(cc + 3, (cc + 3) & 3);

        const uint32_t b0 = sb + (uint32_t)(cc & 3) * H_BYTES + boff0;
        uint32_t bfb[2][8][2];
        ldB(b0, 0, bfb[0]);
#pragma unroll
        for (int t = 0; t < 9; t++) {
            const int cur = t & 1, nxt = cur ^ 1;            // compile-time
            const bool last = (cc == 7) && (t == 8);
            // prefetch next tap's fragments before issuing this tap's mmas
            if (t < 8) ldB(b0, t + 1, bfb[nxt]);
            if (t < 8)      ldA(cc, t + 1, afb[nxt]);
            else if (!last) ldA(cc + 1, 0, afb[nxt]);

#pragma unroll
            for (int mi = 0; mi < 4; mi++)
#pragma unroll
                for (int ni = 0; ni < 8; ni++)
                    mma8(acc[mi][ni], afb[cur][mi], bfb[cur][ni]);
        }
        // after t=8 (even), afb slot for next chunk's t=0 is afb[1];
        // next iteration's t=0 reads afb[0] — so copy once per chunk.
        if (cc < 7) {
#pragma unroll
            for (int mi = 0; mi < 4; mi++) afb[0][mi] = afb[1][mi];
        }
    }

    // ---- epilogue: bias + float2 stores ----
#pragma unroll
    for (int mi = 0; mi < 4; mi++) {
        const int ko0 = warp_m * 64 + mi * 16 + g;
        const float bv0 = __ldg(bias + ko0);
        const float bv1 = __ldg(bias + ko0 + 8);
        float* o0 = out + ((size_t)n * KOUT + ko0) * IMG;
        float* o1 = o0 + 8 * IMG;
#pragma unroll
        for (int ni = 0; ni < 8; ni++) {
            const int p  = warp_n * 64 + ni * 8 + 2 * tig;
            const int oy = py0 + (p >> 4);
            const int ox = px0 + (p & 15);
            const size_t off = (size_t)oy * HW + ox;
            *(float2*)(o0 + off) = make_float2(acc[mi][ni][0] + bv0, acc[mi][ni][1] + bv0);
            *(float2*)(o1 + off) = make_float2(acc[mi][ni][2] + bv1, acc[mi][ni][3] + bv1);
        }
    }
}

extern "C" void kernel_launch(void* const* d_in, const int* in_sizes, int n_in,
                              void* d_out, int out_size)
{
    const float* x = (const float*)d_in[0];
    const float* w = (const float*)d_in[1];
    const float* b = (const float*)d_in[2];
    float* out = (float*)d_out;

    prep_w<<<288, 256>>>(w);

    cudaFuncSetAttribute(conv_mma_wreg2,
                         cudaFuncAttributeMaxDynamicSharedMemorySize, SMEM_TOTAL);
    dim3 grid(49, 32);
    conv_mma_wreg2<<<grid, 256, SMEM_TOTAL>>>(x, b, out);
}

// round 15
// speedup vs baseline: 2.4030x; 2.4030x over previous
#include <cuda_runtime.h>
#include <cuda_fp16.h>
#include <cstdint>

// Conv2d 3x3 s1 p1 NCHW, implicit GEMM, mma.sync m16n8k16 fp16 (fp32 accum).
// A: pre-packed f16x2 fragment-ordered table (g_wtf, L2-resident), LDG.128.
// B: halo tile 16ch x 18x18 in smem (16B cp.async), 4xLDS + f16x2 pack per frag.
// CTA: 128ko x 256px (16x16 tile, one image), 256 thr, 8 warps, warp 64x64.
// K = 576 as 4 chunks of (16 ch x 9 taps); k16-step = 16 channels @ fixed tap.

#define HW    112
#define IMG   (HW * HW)
#define KTOT  576
#define KOUT  128

#define H_ROW   24                       // halo row pitch (words)
#define H_CH    436                      // per-channel words; 2*436%32==8 -> banks ok
#define H_BYTES (16 * H_CH * 4)          // 27904
#define NBUF    4
#define SMEM_TOTAL (NBUF * H_BYTES)      // 111616

// A table: [cc(4)][t(9)][wm(2)][mi(4)][lane(32)] x uint4 (= a0..a3 f16x2)
__device__ uint4 g_wtf[4 * 9 * 2 * 4 * 32];      // 147456 B

__device__ __forceinline__ uint32_t smem_u32(const void* p) {
    uint32_t a;
    asm("{ .reg .u64 t; cvta.to.shared.u64 t, %1; cvt.u32.u64 %0, t; }" : "=r"(a) : "l"(p));
    return a;
}
__device__ __forceinline__ float lds_f32(uint32_t a) {
    float v;
    asm volatile("ld.shared.f32 %0, [%1];" : "=f"(v) : "r"(a));
    return v;
}
// pack {lo,hi} f32 -> f16x2 (lo = first k)
__device__ __forceinline__ uint32_t pk16(float lo, float hi) {
    uint32_t d;
    asm("cvt.rn.f16x2.f32 %0, %2, %1;" : "=r"(d) : "f"(lo), "f"(hi));
    return d;
}
__device__ __forceinline__ void cpa16z(uint32_t dst, const float* src, int sz) {
    asm volatile("cp.async.cg.shared.global [%0], [%1], 16, %2;"
                 :: "r"(dst), "l"(src), "r"(sz));
}
__device__ __forceinline__ void cpa4(uint32_t dst, const float* src, int sz) {
    asm volatile("cp.async.ca.shared.global [%0], [%1], 4, %2;"
                 :: "r"(dst), "l"(src), "r"(sz));
}
__device__ __forceinline__ void mma16(float* d, const uint4& a, const uint32_t* b) {
    asm volatile(
        "mma.sync.aligned.m16n8k16.row.col.f32.f16.f16.f32 "
        "{%0,%1,%2,%3}, {%4,%5,%6,%7}, {%8,%9}, {%0,%1,%2,%3};"
        : "+f"(d[0]), "+f"(d[1]), "+f"(d[2]), "+f"(d[3])
        : "r"(a.x), "r"(a.y), "r"(a.z), "r"(a.w), "r"(b[0]), "r"(b[1]));
}

// ---- prep: w[ko][k] f32 -> g_wtf fragment-ordered f16x2 ----
// uint32 i in [0, 36864): aidx=i&3, lane=(i>>2)&31, mi=(i>>7)&3, wm=(i>>9)&1,
// ct=(i>>10) = cc*9+t.  a0:row g,klo  a1:row g+8,klo  a2:row g,khi  a3:row g+8,khi
__global__ void prep_w(const float* __restrict__ w) {
    const int i    = blockIdx.x * 256 + threadIdx.x;   // 0..36863
    const int aidx = i & 3;
    const int lane = (i >> 2) & 31;
    const int mi   = (i >> 7) & 3;
    const int wm   = (i >> 9) & 1;
    const int ct   = i >> 10;                          // 0..35
    const int cc   = ct / 9;
    const int t    = ct - cc * 9;
    const int g    = lane >> 2;
    const int tig  = lane & 3;
    const int ko   = wm * 64 + mi * 16 + g + 8 * (aidx & 1);
    const int c0   = cc * 16 + 2 * tig + 8 * (aidx >> 1);
    const float v0 = w[ko * KTOT + c0 * 9 + t];
    const float v1 = w[ko * KTOT + (c0 + 1) * 9 + t];
    ((uint32_t*)g_wtf)[i] = pk16(v0, v1);
}

__global__ __launch_bounds__(256, 1)
void conv_mma_f16(const float* __restrict__ x,
                  const float* __restrict__ bias,
                  float* __restrict__ out)
{
    extern __shared__ __align__(16) char dsm[];
    const uint32_t sb = smem_u32(dsm);

    const int tid  = threadIdx.x;
    const int warp = tid >> 5;
    const int lane = tid & 31;
    const int g    = lane >> 2;
    const int tig  = lane & 3;
    const int warp_m = warp >> 2;        // 0..1
    const int warp_n = warp & 3;         // 0..3

    const int tile = blockIdx.x;         // 0..48
    const int n    = blockIdx.y;         // 0..31
    const int py0  = (tile / 7) * 16;
    const int px0  = (tile % 7) * 16;

    const float* xn = x + (size_t)n * 64 * IMG;

    // ---- B staging: 288 (ch,row) pairs; thread does pair tid (+256 if tid<32) ----
    const int  p0ch = tid / 18, p0rw = tid - p0ch * 18;
    const int  p1i  = tid + 256;
    const int  p1ch = p1i / 18, p1rw = p1i - p1ch * 18;
    const bool act1 = (tid < 32);

    const int  gy0  = py0 - 1 + p0rw;
    const bool ok0  = ((unsigned)gy0 < (unsigned)HW);
    const int  so0  = p0ch * IMG + (ok0 ? gy0 : 0) * HW;
    const uint32_t hd0 = (uint32_t)((p0ch * H_CH + p0rw * H_ROW + 3) * 4);

    const int  gy1  = py0 - 1 + p1rw;
    const bool ok1  = act1 && ((unsigned)gy1 < (unsigned)HW);
    const int  so1  = p1ch * IMG + (ok1 ? gy1 : 0) * HW;
    const uint32_t hd1 = (uint32_t)((p1ch * H_CH + p1rw * H_ROW + 3) * 4);

    const bool lok = (px0 > 0), tok = (px0 + 16 < HW);

    auto stage = [&](int cc, int buf) {
        const uint32_t bbase = sb + (uint32_t)buf * H_BYTES;
        {
            const float* sr = xn + cc * 16 * IMG + so0;
            const uint32_t db = bbase + hd0;
            cpa4(db, sr + px0 - 1, (ok0 && lok) ? 4 : 0);
#pragma unroll
            for (int q = 0; q < 4; q++)
                cpa16z(db + (uint32_t)((1 + 4 * q) * 4), sr + px0 + 4 * q, ok0 ? 16 : 0);
            cpa4(db + 17 * 4, sr + px0 + 16, (ok0 && tok) ? 4 : 0);
        }
        if (act1) {
            const float* sr = xn + cc * 16 * IMG + so1;
            const uint32_t db = bbase + hd1;
            cpa4(db, sr + px0 - 1, (ok1 && lok) ? 4 : 0);
#pragma unroll
            for (int q = 0; q < 4; q++)
                cpa16z(db + (uint32_t)((1 + 4 * q) * 4), sr + px0 + 4 * q, ok1 ? 16 : 0);
            cpa4(db + 17 * 4, sr + px0 + 16, (ok1 && tok) ? 4 : 0);
        }
        asm volatile("cp.async.commit_group;" ::: "memory");
    };

    // ---- A fragment load ----
    auto ldA = [&](int cc, int t, uint4 a[4]) {
        const uint4* p = g_wtf + (size_t)(((cc * 9 + t) * 2 + warp_m) * 4) * 32 + lane;
        a[0] = __ldg(p);
        a[1] = __ldg(p + 32);
        a[2] = __ldg(p + 64);
        a[3] = __ldg(p + 96);
    };

    // B fragment base (bytes): word 3 + 2*tig*H_CH + warp_n*4*H_ROW + g
    const uint32_t boff0 = (uint32_t)((3 + 2 * tig * H_CH + warp_n * 4 * H_ROW + g) * 4);

    float acc[4][8][4];
#pragma unroll
    for (int mi = 0; mi < 4; mi++)
#pragma unroll
        for (int ni = 0; ni < 8; ni++)
#pragma unroll
            for (int r = 0; r < 4; r++) acc[mi][ni][r] = 0.0f;

    uint4 afc[4], afn[4];
    ldA(0, 0, afc);

    // ---- pipeline: 4 chunks, depth-3 prefetch ----
    stage(0, 0);
    stage(1, 1);
    stage(2, 2);
#pragma unroll 1
    for (int cc = 0; cc < 4; cc++) {
        if (cc <= 1)      asm volatile("cp.async.wait_group 2;" ::: "memory");
        else if (cc == 2) asm volatile("cp.async.wait_group 1;" ::: "memory");
        else              asm volatile("cp.async.wait_group 0;" ::: "memory");
        __syncthreads();
        if (cc == 0) stage(3, 3);

        const uint32_t b0 = sb + (uint32_t)(cc & 3) * H_BYTES + boff0;
#pragma unroll
        for (int t = 0; t < 9; t++) {
            const int dyt = t / 3, dxt = t - dyt * 3;          // compile-time
            const bool last = (cc == 3) && (t == 8);
            if (t < 8)      ldA(cc, t + 1, afn);
            else if (!last) ldA(cc + 1, 0, afn);

            uint32_t bf[8][2];
#pragma unroll
            for (int ni = 0; ni < 8; ni++) {
                const uint32_t bm = b0 +
                    (uint32_t)((((ni >> 1) + dyt) * H_ROW + (ni & 1) * 8 + dxt) * 4);
                const float v0 = lds_f32(bm);
                const float v1 = lds_f32(bm + H_CH * 4);
                const float v2 = lds_f32(bm + 8 * H_CH * 4);
                const float v3 = lds_f32(bm + 9 * H_CH * 4);
                bf[ni][0] = pk16(v0, v1);
                bf[ni][1] = pk16(v2, v3);
            }
#pragma unroll
            for (int mi = 0; mi < 4; mi++)
#pragma unroll
                for (int ni = 0; ni < 8; ni++)
                    mma16(acc[mi][ni], afc[mi], bf[ni]);
            if (!last) {
#pragma unroll
                for (int mi = 0; mi < 4; mi++) afc[mi] = afn[mi];
            }
        }
    }

    // ---- epilogue: bias + float2 stores ----
#pragma unroll
    for (int mi = 0; mi < 4; mi++) {
        const int ko0 = warp_m * 64 + mi * 16 + g;
        const float bv0 = __ldg(bias + ko0);
        const float bv1 = __ldg(bias + ko0 + 8);
        float* o0 = out + ((size_t)n * KOUT + ko0) * IMG;
        float* o1 = o0 + 8 * IMG;
#pragma unroll
        for (int ni = 0; ni < 8; ni++) {
            const int p  = warp_n * 64 + ni * 8 + 2 * tig;
            const int oy = py0 + (p >> 4);
            const int ox = px0 + (p & 15);
            const size_t off = (size_t)oy * HW + ox;
            *(float2*)(o0 + off) = make_float2(acc[mi][ni][0] + bv0, acc[mi][ni][1] + bv0);
            *(float2*)(o1 + off) = make_float2(acc[mi][ni][2] + bv1, acc[mi][ni][3] + bv1);
        }
    }
}

extern "C" void kernel_launch(void* const* d_in, const int* in_sizes, int n_in,
                              void* d_out, int out_size)
{
    const float* x = (const float*)d_in[0];
    const float* w = (const float*)d_in[1];
    const float* b = (const float*)d_in[2];
    float* out = (float*)d_out;

    prep_w<<<144, 256>>>(w);

    cudaFuncSetAttribute(conv_mma_f16,
                         cudaFuncAttributeMaxDynamicSharedMemorySize, SMEM_TOTAL);
    dim3 grid(49, 32);
    conv_mma_f16<<<grid, 256, SMEM_TOTAL>>>(x, b, out);
}

// round 17
// speedup vs baseline: 2.7713x; 1.1532x over previous
#include <cuda_runtime.h>
#include <cuda_fp16.h>
#include <cstdint>

// Conv2d 3x3 s1 p1 NCHW, implicit GEMM, mma.sync m16n8k16 fp16 (fp32 accum).
// A: pre-packed f16x2 fragment-ordered table (g_wtf, L2-resident), LDG.128.
// B: halo tile 16ch x 10x18 in smem (16B cp.async), 4xLDS + f16x2 pack per frag.
// CTA: 128 threads / 4 warps, tile 128ko x 128px (8x16). TWO CTAs per SM
// (launch_bounds(128,2)) so barrier stalls of one CTA hide under the other.
// K = 576 as 4 chunks of (16 ch x 9 taps); k16-step = 16 channels @ fixed tap.

#define HW    112
#define IMG   (HW * HW)
#define KTOT  576
#define KOUT  128

#define H_ROW   24                       // halo row pitch (words)
#define H_CH    244                      // per-channel words (10*24+4); 2*244%32==8
#define H_BYTES (16 * H_CH * 4)          // 15616
#define NBUF    4
#define SMEM_TOTAL (NBUF * H_BYTES)      // 62464

// A table: [cc(4)][t(9)][wm(2)][mi(4)][lane(32)] x uint4 (= a0..a3 f16x2)
__device__ uint4 g_wtf[4 * 9 * 2 * 4 * 32];      // 147456 B

__device__ __forceinline__ uint32_t smem_u32(const void* p) {
    uint32_t a;
    asm("{ .reg .u64 t; cvta.to.shared.u64 t, %1; cvt.u32.u64 %0, t; }" : "=r"(a) : "l"(p));
    return a;
}
__device__ __forceinline__ float lds_f32(uint32_t a) {
    float v;
    asm volatile("ld.shared.f32 %0, [%1];" : "=f"(v) : "r"(a));
    return v;
}
// pack {lo,hi} f32 -> f16x2 (lo = first k)
__device__ __forceinline__ uint32_t pk16(float lo, float hi) {
    uint32_t d;
    asm("cvt.rn.f16x2.f32 %0, %2, %1;" : "=r"(d) : "f"(lo), "f"(hi));
    return d;
}
__device__ __forceinline__ void cpa16z(uint32_t dst, const float* src, int sz) {
    asm volatile("cp.async.cg.shared.global [%0], [%1], 16, %2;"
                 :: "r"(dst), "l"(src), "r"(sz));
}
__device__ __forceinline__ void cpa4(uint32_t dst, const float* src, int sz) {
    asm volatile("cp.async.ca.shared.global [%0], [%1], 4, %2;"
                 :: "r"(dst), "l"(src), "r"(sz));
}
__device__ __forceinline__ void mma16(float* d, const uint4& a, const uint32_t* b) {
    asm volatile(
        "mma.sync.aligned.m16n8k16.row.col.f32.f16.f16.f32 "
        "{%0,%1,%2,%3}, {%4,%5,%6,%7}, {%8,%9}, {%0,%1,%2,%3};"
        : "+f"(d[0]), "+f"(d[1]), "+f"(d[2]), "+f"(d[3])
        : "r"(a.x), "r"(a.y), "r"(a.z), "r"(a.w), "r"(b[0]), "r"(b[1]));
}

// ---- prep: w[ko][k] f32 -> g_wtf fragment-ordered f16x2 (unchanged layout) ----
__global__ void prep_w(const float* __restrict__ w) {
    const int i    = blockIdx.x * 256 + threadIdx.x;   // 0..36863
    const int aidx = i & 3;
    const int lane = (i >> 2) & 31;
    const int mi   = (i >> 7) & 3;
    const int wm   = (i >> 9) & 1;
    const int ct   = i >> 10;                          // 0..35
    const int cc   = ct / 9;
    const int t    = ct - cc * 9;
    const int g    = lane >> 2;
    const int tig  = lane & 3;
    const int ko   = wm * 64 + mi * 16 + g + 8 * (aidx & 1);
    const int c0   = cc * 16 + 2 * tig + 8 * (aidx >> 1);
    const float v0 = w[ko * KTOT + c0 * 9 + t];
    const float v1 = w[ko * KTOT + (c0 + 1) * 9 + t];
    ((uint32_t*)g_wtf)[i] = pk16(v0, v1);
}

__global__ __launch_bounds__(128, 2)
void conv_mma_f16s(const float* __restrict__ x,
                   const float* __restrict__ bias,
                   float* __restrict__ out)
{
    extern __shared__ __align__(16) char dsm[];
    const uint32_t sb = smem_u32(dsm);

    const int tid  = threadIdx.x;
    const int warp = tid >> 5;
    const int lane = tid & 31;
    const int g    = lane >> 2;
    const int tig  = lane & 3;
    const int warp_m = warp >> 1;        // 0..1 (64 ko)
    const int warp_n = warp & 1;         // 0..1 (64 px)

    const int tile = blockIdx.x;         // 0..97
    const int n    = blockIdx.y;         // 0..31
    const int py0  = (tile / 7) * 8;     // 14 row tiles of 8
    const int px0  = (tile % 7) * 16;    // 7 col tiles of 16

    const float* xn = x + (size_t)n * 64 * IMG;

    // ---- B staging: 160 (ch,row) pairs; thread does pair tid (+128 if tid<32) ----
    const int  p0ch = tid / 10, p0rw = tid - p0ch * 10;
    const int  p1i  = tid + 128;
    const int  p1ch = p1i / 10, p1rw = p1i - p1ch * 10;
    const bool act1 = (tid < 32);

    const int  gy0  = py0 - 1 + p0rw;
    const bool ok0  = ((unsigned)gy0 < (unsigned)HW);
    const int  so0  = p0ch * IMG + (ok0 ? gy0 : 0) * HW;
    const uint32_t hd0 = (uint32_t)((p0ch * H_CH + p0rw * H_ROW + 3) * 4);

    const int  gy1  = py0 - 1 + p1rw;
    const bool ok1  = act1 && ((unsigned)gy1 < (unsigned)HW);
    const int  so1  = p1ch * IMG + (ok1 ? gy1 : 0) * HW;
    const uint32_t hd1 = (uint32_t)((p1ch * H_CH + p1rw * H_ROW + 3) * 4);

    const bool lok = (px0 > 0), tok = (px0 + 16 < HW);

    auto stage = [&](int cc, int buf) {
        const uint32_t bbase = sb + (uint32_t)buf * H_BYTES;
        {
            const float* sr = xn + cc * 16 * IMG + so0;
            const uint32_t db = bbase + hd0;
            cpa4(db, sr + px0 - 1, (ok0 && lok) ? 4 : 0);
#pragma unroll
            for (int q = 0; q < 4; q++)
                cpa16z(db + (uint32_t)((1 + 4 * q) * 4), sr + px0 + 4 * q, ok0 ? 16 : 0);
            cpa4(db + 17 * 4, sr + px0 + 16, (ok0 && tok) ? 4 : 0);
        }
        if (act1) {
            const float* sr = xn + cc * 16 * IMG + so1;
            const uint32_t db = bbase + hd1;
            cpa4(db, sr + px0 - 1, (ok1 && lok) ? 4 : 0);
#pragma unroll
            for (int q = 0; q < 4; q++)
                cpa16z(db + (uint32_t)((1 + 4 * q) * 4), sr + px0 + 4 * q, ok1 ? 16 : 0);
            cpa4(db + 17 * 4, sr + px0 + 16, (ok1 && tok) ? 4 : 0);
        }
        asm volatile("cp.async.commit_group;" ::: "memory");
    };

    // ---- A fragment load ----
    auto ldA = [&](int cc, int t, uint4 a[4]) {
        const uint4* p = g_wtf + (size_t)(((cc * 9 + t) * 2 + warp_m) * 4) * 32 + lane;
        a[0] = __ldg(p);
        a[1] = __ldg(p + 32);
        a[2] = __ldg(p + 64);
        a[3] = __ldg(p + 96);
    };

    // B fragment base (bytes): word 3 + 2*tig*H_CH + warp_n*4*H_ROW + g
    const uint32_t boff0 = (uint32_t)((3 + 2 * tig * H_CH + warp_n * 4 * H_ROW + g) * 4);

    float acc[4][8][4];
#pragma unroll
    for (int mi = 0; mi < 4; mi++)
#pragma unroll
        for (int ni = 0; ni < 8; ni++)
#pragma unroll
            for (int r = 0; r < 4; r++) acc[mi][ni][r] = 0.0f;

    uint4 afc[4], afn[4];
    ldA(0, 0, afc);

    // ---- pipeline: 4 chunks, depth-3 prefetch ----
    stage(0, 0);
    stage(1, 1);
    stage(2, 2);
#pragma unroll 1
    for (int cc = 0; cc < 4; cc++) {
        if (cc <= 1)      asm volatile("cp.async.wait_group 2;" ::: "memory");
        else if (cc == 2) asm volatile("cp.async.wait_group 1;" ::: "memory");
        else              asm volatile("cp.async.wait_group 0;" ::: "memory");
        __syncthreads();
        if (cc == 0) stage(3, 3);

        const uint32_t b0 = sb + (uint32_t)(cc & 3) * H_BYTES + boff0;
#pragma unroll
        for (int t = 0; t < 9; t++) {
            const int dyt = t / 3, dxt = t - dyt * 3;          // compile-time
            const bool last = (cc == 3) && (t == 8);
            if (t < 8)      ldA(cc, t + 1, afn);
            else if (!last) ldA(cc + 1, 0, afn);

            uint32_t bf[8][2];
#pragma unroll
            for (int ni = 0; ni < 8; ni++) {
                const uint32_t bm = b0 +
                    (uint32_t)((((ni >> 1) + dyt) * H_ROW + (ni & 1) * 8 + dxt) * 4);
                const float v0 = lds_f32(bm);
                const float v1 = lds_f32(bm + H_CH * 4);
                const float v2 = lds_f32(bm + 8 * H_CH * 4);
                const float v3 = lds_f32(bm + 9 * H_CH * 4);
                bf[ni][0] = pk16(v0, v1);
                bf[ni][1] = pk16(v2, v3);
            }
#pragma unroll
            for (int mi = 0; mi < 4; mi++)
#pragma unroll
                for (int ni = 0; ni < 8; ni++)
                    mma16(acc[mi][ni], afc[mi], bf[ni]);
            if (!last) {
#pragma unroll
                for (int mi = 0; mi < 4; mi++) afc[mi] = afn[mi];
            }
        }
    }

    // ---- epilogue: bias + float2 stores ----
#pragma unroll
    for (int mi = 0; mi < 4; mi++) {
        const int ko0 = warp_m * 64 + mi * 16 + g;
        const float bv0 = __ldg(bias + ko0);
        const float bv1 = __ldg(bias + ko0 + 8);
        float* o0 = out + ((size_t)n * KOUT + ko0) * IMG;
        float* o1 = o0 + 8 * IMG;
#pragma unroll
        for (int ni = 0; ni < 8; ni++) {
            const int p  = warp_n * 64 + ni * 8 + 2 * tig;
            const int oy = py0 + (p >> 4);
            const int ox = px0 + (p & 15);
            const size_t off = (size_t)oy * HW + ox;
            *(float2*)(o0 + off) = make_float2(acc[mi][ni][0] + bv0, acc[mi][ni][1] + bv0);
            *(float2*)(o1 + off) = make_float2(acc[mi][ni][2] + bv1, acc[mi][ni][3] + bv1);
        }
    }
}

extern "C" void kernel_launch(void* const* d_in, const int* in_sizes, int n_in,
                              void* d_out, int out_size)
{
    const float* x = (const float*)d_in[0];
    const float* w = (const float*)d_in[1];
    const float* b = (const float*)d_in[2];
    float* out = (float*)d_out;

    prep_w<<<144, 256>>>(w);

    cudaFuncSetAttribute(conv_mma_f16s,
                         cudaFuncAttributeMaxDynamicSharedMemorySize, SMEM_TOTAL);
    dim3 grid(98, 32);
    conv_mma_f16s<<<grid, 128, SMEM_TOTAL>>>(x, b, out);
}